// round 3
// baseline (speedup 1.0000x reference)
#include <cuda_runtime.h>
#include <cstdint>

// ---------------------------------------------------------------------------
// LinearPatchMerger on GB300, family-target-safe (no tcgen05 / no TMA):
//   out[32768,1024] = A[32768,4096] @ Wperm^T
//   A row n = concat of 4 contiguous 1024-float source rows of image_features
//   Wperm[dout, q*1024+d] = rna_tf32(W[dout, d*4+q])
// GEMM: mma.sync.aligned.m16n8k8.tf32 + cp.async, 3-stage pipeline.
// ---------------------------------------------------------------------------

constexpr int K_TOT = 4096;
constexpr int N_TOT = 1024;

constexpr int MT = 128;            // CTA M tile
constexpr int NTC = 128;           // CTA N tile
constexpr int KC = 32;             // K per stage
constexpr int NCHUNK = K_TOT / KC; // 128
constexpr int NSTAGE = 3;
constexpr int THREADS = 256;

constexpr int A_BYTES = MT * KC * 4;            // 16 KB
constexpr int B_BYTES = NTC * KC * 4;           // 16 KB
constexpr int STAGE = A_BYTES + B_BYTES;        // 32 KB
constexpr int SMEM_BYTES = NSTAGE * STAGE;      // 96 KB

__device__ float g_Wp[N_TOT * K_TOT];           // 16 MB permuted tf32 weights

#define DEV __device__ __forceinline__

DEV uint32_t smem_u32(const void* p) {
    uint32_t a;
    asm("{ .reg .u64 t; cvta.to.shared.u64 t, %1; cvt.u32.u64 %0, t; }"
        : "=r"(a) : "l"(p));
    return a;
}
DEV uint32_t tf32r(float f) {
    uint32_t t;
    asm("cvt.rna.tf32.f32 %0, %1;" : "=r"(t) : "f"(f));
    return t;
}
DEV void cp16(uint32_t dst, const void* src) {
    asm volatile("cp.async.ca.shared.global [%0], [%1], 16;"
                 :: "r"(dst), "l"(src) : "memory");
}
DEV void cp_commit() { asm volatile("cp.async.commit_group;" ::: "memory"); }
template <int N> DEV void cp_wait() {
    asm volatile("cp.async.wait_group %0;" :: "n"(N) : "memory");
}
DEV uint32_t lds32(uint32_t a) {
    uint32_t v;
    asm volatile("ld.shared.b32 %0, [%1];" : "=r"(v) : "r"(a));
    return v;
}
DEV void mma_tf32(float* d, const uint32_t* a, const uint32_t* b) {
    asm volatile(
        "mma.sync.aligned.m16n8k8.row.col.f32.tf32.tf32.f32 "
        "{%0,%1,%2,%3}, {%4,%5,%6,%7}, {%8,%9}, {%0,%1,%2,%3};"
        : "+f"(d[0]), "+f"(d[1]), "+f"(d[2]), "+f"(d[3])
        : "r"(a[0]), "r"(a[1]), "r"(a[2]), "r"(a[3]), "r"(b[0]), "r"(b[1]));
}

// ---------------------------------------------------------------------------
// Prep: permute + RNA-tf32-round W:  g_Wp[dout][q*1024+d] = rna(W[dout][4d+q])
// ---------------------------------------------------------------------------
__global__ void prep_w_kernel(const float* __restrict__ W) {
    int stride = gridDim.x * blockDim.x;
    for (int o = blockIdx.x * blockDim.x + threadIdx.x;
         o < N_TOT * K_TOT; o += stride) {
        int dout = o >> 12;
        int rem  = o & 4095;
        int q    = rem >> 10;
        int d    = rem & 1023;
        g_Wp[o]  = __uint_as_float(tf32r(W[(dout << 12) + (d << 2) + q]));
    }
}

// ---------------------------------------------------------------------------
// Main GEMM: grid (8 n-tiles, 256 m-tiles), 256 threads, warps 2(m) x 4(n),
// warp tile 64x32, mma m16n8k8 tf32.
// SMEM swizzle: float col c of row r stored at col  c ^ ((r&7)<<2).
// ---------------------------------------------------------------------------
__global__ void __launch_bounds__(THREADS, 2)
merger_gemm_kernel(const float* __restrict__ X, float* __restrict__ out) {
    extern __shared__ __align__(1024) char sm[];
    const uint32_t sbase = smem_u32(sm);

    const int tid = threadIdx.x;
    const int wid = tid >> 5;
    const int lid = tid & 31;
    const int bx  = blockIdx.x;    // n-tile 0..7
    const int mt  = blockIdx.y;    // m-tile 0..255

    const int warp_m = wid & 1;    // 0..1  (64 rows each)
    const int warp_n = wid >> 1;   // 0..3  (32 cols each)
    const int g   = lid >> 2;      // group id 0..7
    const int tig = lid & 3;       // thread-in-group

    // ---- producer (cp.async) slot precompute ----
    // A: 128 rows x 8 float4 = 1024 slots, 4 per thread
    int rbA[4], ldA4[4];
    uint32_t stsA[4], stsB[4];
    int ldB[4];
    #pragma unroll
    for (int k2 = 0; k2 < 4; k2++) {
        int f  = tid + (k2 << 8);
        int m  = f >> 3;                         // row 0..127
        int c4 = f & 7;                          // 16B segment
        int i  = ((mt & 31) << 1) + (m >> 6);    // merged i
        int j  = m & 63;                         // merged j
        rbA[k2]  = (i << 8) + (j << 1);          // patch row base (sans q)
        ldA4[k2] = c4 << 2;
        stsA[k2] = (uint32_t)(m * 128 + ((c4 ^ (m & 7)) << 4));
        ldB[k2]  = m * K_TOT + (c4 << 2);        // B row m, same c4
        stsB[k2] = stsA[k2];
    }

    const float* Xi = X + (size_t)(mt >> 5) * (16384u * 1024u);
    const float* Wb = g_Wp + (size_t)bx * NTC * K_TOT;

    // ---- consumer (LDS) base offsets ----
    const uint32_t colsw = (uint32_t)((tig ^ (g << 2)) << 2);  // swizzled col bytes
    const uint32_t offA  = (uint32_t)((warp_m * 64 + g) * 128) + colsw;
    const uint32_t offB  = (uint32_t)((warp_n * 32 + g) * 128) + colsw;

    float acc[4][4][4];
    #pragma unroll
    for (int mi = 0; mi < 4; mi++)
        #pragma unroll
        for (int ni = 0; ni < 4; ni++)
            #pragma unroll
            for (int r = 0; r < 4; r++) acc[mi][ni][r] = 0.0f;

    // ---- stage loader ----
    auto load_stage = [&](int st, int kc) {
        const int q    = kc >> 5;
        const int d0   = (kc & 31) << 5;
        const int qrow = ((q >> 1) << 7) + (q & 1);
        const uint32_t aS = sbase + st * STAGE;
        const uint32_t bS = aS + A_BYTES;
        #pragma unroll
        for (int k2 = 0; k2 < 4; k2++)
            cp16(aS + stsA[k2],
                 Xi + (size_t)(rbA[k2] + qrow) * 1024 + d0 + ldA4[k2]);
        #pragma unroll
        for (int k2 = 0; k2 < 4; k2++)
            cp16(bS + stsB[k2], Wb + ldB[k2] + (kc << 5));
    };

    // ---- prologue ----
    #pragma unroll
    for (int s = 0; s < NSTAGE - 1; s++) { load_stage(s, s); cp_commit(); }
    int kc_load = NSTAGE - 1;

    // ---- mainloop ----
    for (int kc = 0; kc < NCHUNK; kc++) {
        cp_wait<NSTAGE - 2>();
        __syncthreads();

        if (kc_load < NCHUNK) { load_stage(kc_load % NSTAGE, kc_load); kc_load++; }
        cp_commit();

        const uint32_t aS = sbase + (kc % NSTAGE) * STAGE;
        const uint32_t bS = aS + A_BYTES;

        #pragma unroll
        for (int s = 0; s < 4; s++) {
            const uint32_t sx = (uint32_t)(s << 5);  // k8 step: XOR on col bits 5..6
            uint32_t afr[4][4];
            #pragma unroll
            for (int mi = 0; mi < 4; mi++) {
                uint32_t a0 = (aS + offA + mi * 2048) ^ sx;
                afr[mi][0] = lds32(a0);
                afr[mi][1] = lds32(a0 + 1024);
                afr[mi][2] = lds32(a0 ^ 16);
                afr[mi][3] = lds32((a0 ^ 16) + 1024);
            }
            uint32_t bfr[4][2];
            #pragma unroll
            for (int ni = 0; ni < 4; ni++) {
                uint32_t b0 = (bS + offB + ni * 1024) ^ sx;
                bfr[ni][0] = lds32(b0);
                bfr[ni][1] = lds32(b0 ^ 16);
            }
            #pragma unroll
            for (int mi = 0; mi < 4; mi++)
                #pragma unroll
                for (int ni = 0; ni < 4; ni++)
                    mma_tf32(acc[mi][ni], afr[mi], bfr[ni]);
        }
    }

    // ---- epilogue: direct STG.64 (c0,c1 adjacent cols) ----
    const int row0 = mt * 128 + warp_m * 64 + g;
    const int col0 = bx * 128 + warp_n * 32 + tig * 2;
    #pragma unroll
    for (int mi = 0; mi < 4; mi++) {
        #pragma unroll
        for (int ni = 0; ni < 4; ni++) {
            float* p0 = out + (size_t)(row0 + mi * 16) * N_TOT + col0 + ni * 8;
            float* p1 = p0 + 8 * N_TOT;
            *(float2*)p0 = make_float2(acc[mi][ni][0], acc[mi][ni][1]);
            *(float2*)p1 = make_float2(acc[mi][ni][2], acc[mi][ni][3]);
        }
    }
}

// ---------------------------------------------------------------------------
extern "C" void kernel_launch(void* const* d_in, const int* in_sizes, int n_in,
                              void* d_out, int out_size) {
    (void)in_sizes; (void)n_in; (void)out_size;
    const float* X = (const float*)d_in[0];   // (1,131072,1024) f32
    const float* W = (const float*)d_in[2];   // (1024,4096) f32
    float* out = (float*)d_out;               // (1,32768,1024) f32

    cudaFuncSetAttribute(merger_gemm_kernel,
                         cudaFuncAttributeMaxDynamicSharedMemorySize, SMEM_BYTES);

    prep_w_kernel<<<512, 256>>>(W);
    merger_gemm_kernel<<<dim3(8, 256, 1), THREADS, SMEM_BYTES>>>(X, out);
}

// round 6
// speedup vs baseline: 2.1055x; 2.1055x over previous
#include <cuda_runtime.h>
#include <cuda_fp16.h>
#include <cstdint>

// ---------------------------------------------------------------------------
// LinearPatchMerger (GB300, family-safe):
//   prep:  g_Xh[32768][4096] = fp16( unfold-permuted image_features )
//          g_Wh[1024][4096]  = fp16( column-permuted W )
//   gemm:  out[32768,1024] = g_Xh @ g_Wh^T   via mma.m16n8k16.f16 (f32 accum)
// ---------------------------------------------------------------------------

constexpr int K_TOT = 4096;
constexpr int N_TOT = 1024;
constexpr int M_TOT = 32768;

constexpr int KC = 64;               // K halves per stage (128 B rows)
constexpr int NCHUNK = K_TOT / KC;   // 64
constexpr int NSTAGE = 3;
constexpr int THREADS = 128;         // 4 warps, 2x2 of 64x64 warp tiles

constexpr int A_BYTES = 128 * KC * 2;        // 16 KB
constexpr int B_BYTES = 128 * KC * 2;        // 16 KB
constexpr int STAGE   = A_BYTES + B_BYTES;   // 32 KB
constexpr int SMEM_BYTES = NSTAGE * STAGE;   // 96 KB

__device__ __half g_Xh[(size_t)M_TOT * K_TOT];  // 268 MB permuted fp16 A
__device__ __half g_Wh[(size_t)N_TOT * K_TOT];  // 8 MB permuted fp16 W

#define DEV __device__ __forceinline__

DEV uint32_t smem_u32(const void* p) {
    uint32_t a;
    asm("{ .reg .u64 t; cvta.to.shared.u64 t, %1; cvt.u32.u64 %0, t; }"
        : "=r"(a) : "l"(p));
    return a;
}
DEV void cp16(uint32_t dst, const void* src) {
    asm volatile("cp.async.ca.shared.global [%0], [%1], 16;"
                 :: "r"(dst), "l"(src) : "memory");
}
DEV void cp_commit() { asm volatile("cp.async.commit_group;" ::: "memory"); }
template <int N> DEV void cp_wait() {
    asm volatile("cp.async.wait_group %0;" :: "n"(N) : "memory");
}
DEV void ldmx4(uint32_t* r, uint32_t a) {
    asm volatile("ldmatrix.sync.aligned.m8n8.x4.shared.b16 {%0,%1,%2,%3}, [%4];"
                 : "=r"(r[0]), "=r"(r[1]), "=r"(r[2]), "=r"(r[3]) : "r"(a));
}
DEV void mma_f16(float* d, const uint32_t* a, uint32_t b0, uint32_t b1) {
    asm volatile(
        "mma.sync.aligned.m16n8k16.row.col.f32.f16.f16.f32 "
        "{%0,%1,%2,%3}, {%4,%5,%6,%7}, {%8,%9}, {%0,%1,%2,%3};"
        : "+f"(d[0]), "+f"(d[1]), "+f"(d[2]), "+f"(d[3])
        : "r"(a[0]), "r"(a[1]), "r"(a[2]), "r"(a[3]), "r"(b0), "r"(b1));
}

// ---------------------------------------------------------------------------
// prep W: g_Wh[dout][q*1024+d] = fp16( W[dout][4d+q] )
// ---------------------------------------------------------------------------
__global__ void prep_w_kernel(const float* __restrict__ W) {
    int stride = gridDim.x * blockDim.x;
    for (int o = blockIdx.x * blockDim.x + threadIdx.x;
         o < N_TOT * K_TOT; o += stride) {
        int dout = o >> 12;
        int rem  = o & 4095;
        int q    = rem >> 10;
        int d    = rem & 1023;
        g_Wh[o]  = __float2half_rn(W[(dout << 12) + (d << 2) + q]);
    }
}

// ---------------------------------------------------------------------------
// prep X: g_Xh[n][q*1024+d] = fp16( X[srcrow(n,q)][d] )
// One unit = 8 output halves (16 B store) from 2 float4 loads. Fully coalesced.
// ---------------------------------------------------------------------------
__global__ void prep_x_kernel(const float* __restrict__ X) {
    const int total = M_TOT * (K_TOT / 8);          // 16.78M units
    int stride = gridDim.x * blockDim.x;
    for (int o = blockIdx.x * blockDim.x + threadIdx.x; o < total; o += stride) {
        int n  = o >> 9;                 // out row
        int rh = (o & 511) << 3;         // half offset within 4096
        int q  = rh >> 10;
        int d0 = rh & 1023;
        int im = n >> 12, ml = n & 4095;
        int i = ml >> 6, j = ml & 63;
        int src = (im << 14) + (((i << 1) + (q >> 1)) << 7) + (j << 1) + (q & 1);
        const float4* p = (const float4*)(X + ((size_t)src << 10) + d0);
        float4 v0 = p[0], v1 = p[1];
        __half2 h[4] = {
            __floats2half2_rn(v0.x, v0.y), __floats2half2_rn(v0.z, v0.w),
            __floats2half2_rn(v1.x, v1.y), __floats2half2_rn(v1.z, v1.w)};
        *(uint4*)(g_Xh + ((size_t)o << 3)) = *(const uint4*)h;
    }
}

// ---------------------------------------------------------------------------
// GEMM: grid (8 n-tiles, 256 m-tiles), 128 threads, warp tile 64x64,
// mma m16n8k16 fp16/f32. smem rows = 64 halves (128 B), chunk swizzle c^( r&7 ).
// ---------------------------------------------------------------------------
__global__ void __launch_bounds__(THREADS, 2)
merger_gemm_kernel(float* __restrict__ out) {
    extern __shared__ __align__(1024) char sm[];
    const uint32_t sbase = smem_u32(sm);

    const int tid = threadIdx.x;
    const int wid = tid >> 5;
    const int lid = tid & 31;
    const int bx  = blockIdx.x;     // n-tile 0..7
    const int mt  = blockIdx.y;     // m-tile 0..255

    const int warp_m = wid & 1;     // 64-row half
    const int warp_n = wid >> 1;    // 64-col half
    const int g   = lid >> 2;
    const int tig = lid & 3;

    // ---- producer slots: 16 cp16 / thread / stage (8 A + 8 B) ----
    uint32_t stsOff[8];
    const __half *srcA[8], *srcB[8];
    #pragma unroll
    for (int k2 = 0; k2 < 8; k2++) {
        int f = tid + (k2 << 7);             // 0..1023
        int r = f >> 3;                      // row 0..127
        int c = f & 7;                       // 16B chunk
        stsOff[k2] = (uint32_t)(r * 128 + ((c ^ (r & 7)) << 4));
        srcA[k2] = g_Xh + ((size_t)(mt * 128 + r) << 12) + (c << 3);
        srcB[k2] = g_Wh + ((size_t)(bx * 128 + r) << 12) + (c << 3);
    }

    // ---- consumer ldmatrix lane geometry ----
    // A x4: row = base + (l&15), chunk = 2s + (l>>4)
    const int rA  = (lid & 15);
    const int cbA = lid >> 4;
    // B x4: row = base + ((l>>4)<<3) + (l&7), chunk = 2s + ((l>>3)&1)
    const int rB  = ((lid >> 4) << 3) + (lid & 7);
    const int cbB = (lid >> 3) & 1;

    float acc[4][8][4];
    #pragma unroll
    for (int mi = 0; mi < 4; mi++)
        #pragma unroll
        for (int ni = 0; ni < 8; ni++)
            #pragma unroll
            for (int r = 0; r < 4; r++) acc[mi][ni][r] = 0.0f;

    auto load_stage = [&](int st, int kc) {
        const uint32_t aS = sbase + st * STAGE;
        const uint32_t bS = aS + A_BYTES;
        #pragma unroll
        for (int k2 = 0; k2 < 8; k2++) cp16(aS + stsOff[k2], srcA[k2] + kc * KC);
        #pragma unroll
        for (int k2 = 0; k2 < 8; k2++) cp16(bS + stsOff[k2], srcB[k2] + kc * KC);
    };

    #pragma unroll
    for (int s = 0; s < NSTAGE - 1; s++) { load_stage(s, s); cp_commit(); }
    int kc_load = NSTAGE - 1;

    for (int kc = 0; kc < NCHUNK; kc++) {
        cp_wait<NSTAGE - 2>();
        __syncthreads();

        if (kc_load < NCHUNK) { load_stage(kc_load % NSTAGE, kc_load); kc_load++; }
        cp_commit();

        const uint32_t aS = sbase + (kc % NSTAGE) * STAGE;
        const uint32_t bS = aS + A_BYTES;

        #pragma unroll
        for (int s = 0; s < 4; s++) {
            uint32_t afr[4][4];
            #pragma unroll
            for (int mi = 0; mi < 4; mi++) {
                int row = warp_m * 64 + mi * 16 + rA;
                int ch  = (2 * s + cbA) ^ (row & 7);
                ldmx4(afr[mi], aS + row * 128 + (ch << 4));
            }
            uint32_t bfr[4][4];
            #pragma unroll
            for (int nj = 0; nj < 4; nj++) {
                int row = warp_n * 64 + nj * 16 + rB;
                int ch  = (2 * s + cbB) ^ (row & 7);
                ldmx4(bfr[nj], bS + row * 128 + (ch << 4));
            }
            #pragma unroll
            for (int mi = 0; mi < 4; mi++)
                #pragma unroll
                for (int ni = 0; ni < 8; ni++)
                    mma_f16(acc[mi][ni], afr[mi],
                            bfr[ni >> 1][(ni & 1) * 2],
                            bfr[ni >> 1][(ni & 1) * 2 + 1]);
        }
    }

    // ---- epilogue: direct STG.64 ----
    const int row0 = mt * 128 + warp_m * 64 + g;
    const int col0 = bx * 128 + warp_n * 64 + tig * 2;
    #pragma unroll
    for (int mi = 0; mi < 4; mi++) {
        #pragma unroll
        for (int ni = 0; ni < 8; ni++) {
            float* p0 = out + (size_t)(row0 + mi * 16) * N_TOT + col0 + ni * 8;
            *(float2*)p0             = make_float2(acc[mi][ni][0], acc[mi][ni][1]);
            *(float2*)(p0 + 8*N_TOT) = make_float2(acc[mi][ni][2], acc[mi][ni][3]);
        }
    }
}

// ---------------------------------------------------------------------------
extern "C" void kernel_launch(void* const* d_in, const int* in_sizes, int n_in,
                              void* d_out, int out_size) {
    (void)in_sizes; (void)n_in; (void)out_size;
    const float* X = (const float*)d_in[0];   // (1,131072,1024) f32
    const float* W = (const float*)d_in[2];   // (1024,4096) f32
    float* out = (float*)d_out;               // (1,32768,1024) f32

    cudaFuncSetAttribute(merger_gemm_kernel,
                         cudaFuncAttributeMaxDynamicSharedMemorySize, SMEM_BYTES);

    prep_w_kernel<<<128, 256>>>(W);
    prep_x_kernel<<<4096, 256>>>(X);
    merger_gemm_kernel<<<dim3(8, 256, 1), THREADS, SMEM_BYTES>>>(out);
}